// round 12
// baseline (speedup 1.0000x reference)
#include <cuda_runtime.h>
#include <math.h>

#define TT    1024
#define BATCH 1024
#define HDIM  100
#define GDIM  400
#define BPB   8              // batch elems per block
#define NB1   (BATCH / BPB)  // 128 persistent blocks
#define NT1   200            // thread <-> (j0 in 0..99, bh in 0..1); 4 batch/thread

typedef unsigned long long u64;

__device__ float g_h1[(size_t)TT * BATCH * HDIM];    // layer-0 hidden states
__device__ float g_pre1[(size_t)TT * BATCH * GDIM];  // layer-1 gate pre-activations

__device__ __forceinline__ float sigmf(float x) { return 1.0f / (1.0f + __expf(-x)); }
__device__ __forceinline__ float tanh_fast(float x) {
    float t = __expf(2.0f * x);
    return 1.0f - __fdividef(2.0f, t + 1.0f);
}
__device__ __forceinline__ u64 ffma2(u64 a, u64 b, u64 c) {
    u64 d;
    asm("fma.rn.f32x2 %0, %1, %2, %3;" : "=l"(d) : "l"(a), "l"(b), "l"(c));
    return d;
}
__device__ __forceinline__ float hsum2(u64 v) {
    float lo, hi;
    asm("mov.b64 {%0, %1}, %2;" : "=f"(lo), "=f"(hi) : "l"(v));
    return lo + hi;
}

// ============================================================================
// Layer-0 recurrence. Thread owns (j0, batch-half): all 4 gates x 4 batch.
// Per k4 iter: 8 LDS.128 -> 32 FFMA2 (1.5 B/MAC). One barrier/step.
// ============================================================================
__global__ void __launch_bounds__(NT1, 1) lstm_layer0_kernel(
    const float* __restrict__ x,      // [1024][3][1024]
    const float* __restrict__ Wih,    // [400][3]
    const float* __restrict__ Whh,    // [400][100]
    const float* __restrict__ bih,
    const float* __restrict__ bhh)
{
    extern __shared__ float sm[];
    float* sW    = sm;                   // 400*100
    float* sWin  = sW + GDIM * HDIM;     // 400*4
    float* sBias = sWin + GDIM * 4;      // 400
    float* sH0   = sBias + GDIM;         // 800
    float* sH1   = sH0 + BPB * HDIM;     // 800

    const int tid = threadIdx.x;
    const int j0  = tid >> 1;            // 0..99
    const int bh  = tid & 1;             // batch half
    const int bB  = 4 * bh;              // batch base: 0 or 4
    const int bg0 = blockIdx.x * BPB;

    for (int lin = tid; lin < GDIM * HDIM; lin += NT1) sW[lin] = Whh[lin];
    for (int lin = tid; lin < GDIM * 3; lin += NT1)
        sWin[(lin / 3) * 4 + (lin % 3)] = Wih[lin];
    for (int lin = tid; lin < GDIM; lin += NT1) sBias[lin] = bih[lin] + bhh[lin];
    for (int lin = tid; lin < BPB * HDIM; lin += NT1) sH0[lin] = 0.0f;
    __syncthreads();

    float bi[4], wi[4][3];
    #pragma unroll
    for (int g = 0; g < 4; g++) {
        bi[g] = sBias[g * HDIM + j0];
        wi[g][0] = sWin[(g * HDIM + j0) * 4 + 0];
        wi[g][1] = sWin[(g * HDIM + j0) * 4 + 1];
        wi[g][2] = sWin[(g * HDIM + j0) * 4 + 2];
    }
    const ulonglong2* wp0 = (const ulonglong2*)(sW + (0 * HDIM + j0) * HDIM);
    const ulonglong2* wp1 = (const ulonglong2*)(sW + (1 * HDIM + j0) * HDIM);
    const ulonglong2* wp2 = (const ulonglong2*)(sW + (2 * HDIM + j0) * HDIM);
    const ulonglong2* wp3 = (const ulonglong2*)(sW + (3 * HDIM + j0) * HDIM);
    const float* xp0 = x + (size_t)(bg0 + bB + 0) * 3072;
    const float* xp1 = x + (size_t)(bg0 + bB + 1) * 3072;
    const float* xp2 = x + (size_t)(bg0 + bB + 2) * 3072;
    const float* xp3 = x + (size_t)(bg0 + bB + 3) * 3072;

    float c[4] = {0.0f, 0.0f, 0.0f, 0.0f};
    float* sHr = sH0;
    float* sHw = sH1;

    for (int t = 0; t < TT; t++) {
        float xv[4][3];
        xv[0][0] = xp0[t]; xv[0][1] = xp0[1024 + t]; xv[0][2] = xp0[2048 + t];
        xv[1][0] = xp1[t]; xv[1][1] = xp1[1024 + t]; xv[1][2] = xp1[2048 + t];
        xv[2][0] = xp2[t]; xv[2][1] = xp2[1024 + t]; xv[2][2] = xp2[2048 + t];
        xv[3][0] = xp3[t]; xv[3][1] = xp3[1024 + t]; xv[3][2] = xp3[2048 + t];

        u64 acc[4][4];   // [gate][batch]
        #pragma unroll
        for (int g = 0; g < 4; g++)
            #pragma unroll
            for (int u = 0; u < 4; u++) acc[g][u] = 0ULL;

        const ulonglong2* hp0 = (const ulonglong2*)(sHr + (bB + 0) * HDIM);
        const ulonglong2* hp1 = (const ulonglong2*)(sHr + (bB + 1) * HDIM);
        const ulonglong2* hp2 = (const ulonglong2*)(sHr + (bB + 2) * HDIM);
        const ulonglong2* hp3 = (const ulonglong2*)(sHr + (bB + 3) * HDIM);

        #pragma unroll
        for (int k4 = 0; k4 < HDIM / 4; k4++) {
            ulonglong2 h0 = hp0[k4];
            ulonglong2 h1 = hp1[k4];
            ulonglong2 h2 = hp2[k4];
            ulonglong2 h3 = hp3[k4];
            ulonglong2 w;
            w = wp0[k4];
            acc[0][0] = ffma2(w.x, h0.x, acc[0][0]); acc[0][0] = ffma2(w.y, h0.y, acc[0][0]);
            acc[0][1] = ffma2(w.x, h1.x, acc[0][1]); acc[0][1] = ffma2(w.y, h1.y, acc[0][1]);
            acc[0][2] = ffma2(w.x, h2.x, acc[0][2]); acc[0][2] = ffma2(w.y, h2.y, acc[0][2]);
            acc[0][3] = ffma2(w.x, h3.x, acc[0][3]); acc[0][3] = ffma2(w.y, h3.y, acc[0][3]);
            w = wp1[k4];
            acc[1][0] = ffma2(w.x, h0.x, acc[1][0]); acc[1][0] = ffma2(w.y, h0.y, acc[1][0]);
            acc[1][1] = ffma2(w.x, h1.x, acc[1][1]); acc[1][1] = ffma2(w.y, h1.y, acc[1][1]);
            acc[1][2] = ffma2(w.x, h2.x, acc[1][2]); acc[1][2] = ffma2(w.y, h2.y, acc[1][2]);
            acc[1][3] = ffma2(w.x, h3.x, acc[1][3]); acc[1][3] = ffma2(w.y, h3.y, acc[1][3]);
            w = wp2[k4];
            acc[2][0] = ffma2(w.x, h0.x, acc[2][0]); acc[2][0] = ffma2(w.y, h0.y, acc[2][0]);
            acc[2][1] = ffma2(w.x, h1.x, acc[2][1]); acc[2][1] = ffma2(w.y, h1.y, acc[2][1]);
            acc[2][2] = ffma2(w.x, h2.x, acc[2][2]); acc[2][2] = ffma2(w.y, h2.y, acc[2][2]);
            acc[2][3] = ffma2(w.x, h3.x, acc[2][3]); acc[2][3] = ffma2(w.y, h3.y, acc[2][3]);
            w = wp3[k4];
            acc[3][0] = ffma2(w.x, h0.x, acc[3][0]); acc[3][0] = ffma2(w.y, h0.y, acc[3][0]);
            acc[3][1] = ffma2(w.x, h1.x, acc[3][1]); acc[3][1] = ffma2(w.y, h1.y, acc[3][1]);
            acc[3][2] = ffma2(w.x, h2.x, acc[3][2]); acc[3][2] = ffma2(w.y, h2.y, acc[3][2]);
            acc[3][3] = ffma2(w.x, h3.x, acc[3][3]); acc[3][3] = ffma2(w.y, h3.y, acc[3][3]);
        }

        size_t rowbase = (size_t)t * BATCH + bg0 + bB;
        #pragma unroll
        for (int u = 0; u < 4; u++) {
            float gi = hsum2(acc[0][u]) + bi[0]
                     + wi[0][0]*xv[u][0] + wi[0][1]*xv[u][1] + wi[0][2]*xv[u][2];
            float gf = hsum2(acc[1][u]) + bi[1]
                     + wi[1][0]*xv[u][0] + wi[1][1]*xv[u][1] + wi[1][2]*xv[u][2];
            float gg = hsum2(acc[2][u]) + bi[2]
                     + wi[2][0]*xv[u][0] + wi[2][1]*xv[u][1] + wi[2][2]*xv[u][2];
            float go = hsum2(acc[3][u]) + bi[3]
                     + wi[3][0]*xv[u][0] + wi[3][1]*xv[u][1] + wi[3][2]*xv[u][2];
            c[u] = sigmf(gf) * c[u] + sigmf(gi) * tanh_fast(gg);
            float hv = sigmf(go) * tanh_fast(c[u]);
            sHw[(bB + u) * HDIM + j0] = hv;
            g_h1[(rowbase + u) * HDIM + j0] = hv;
        }

        float* tmp = sHr; sHr = sHw; sHw = tmp;
        __syncthreads();
    }
}

// ============================================================================
// Layer-1 input GEMM: pre1[r][j] = bias[j] + sum_k h1[r][k]*W_ih1[j][k]
// (R5 version: 128x80 tile, 256 threads, thread tile 8x5, f32x2 k-pairs)
// ============================================================================
#define GA_MT 128
#define GA_NT 80
__global__ void __launch_bounds__(256, 2) gemm_ih1_kernel(
    const float* __restrict__ W,      // [400][100]
    const float* __restrict__ bih,
    const float* __restrict__ bhh)
{
    extern __shared__ float sm[];
    float* sA = sm;                   // 128*100
    float* sB = sA + GA_MT * HDIM;    // 80*102

    const int tid = threadIdx.x;
    const size_t rbase = (size_t)blockIdx.y * GA_MT;
    const int cbase = blockIdx.x * GA_NT;

    for (int lin = tid; lin < GA_MT * HDIM; lin += 256)
        sA[lin] = g_h1[rbase * HDIM + lin];
    for (int lin = tid; lin < GA_NT * HDIM; lin += 256)
        sB[(lin / HDIM) * 102 + (lin % HDIM)] = W[(size_t)cbase * HDIM + lin];
    __syncthreads();

    const int tx = tid & 15;
    const int ty = tid >> 4;

    u64 acc[8][5];
    #pragma unroll
    for (int i = 0; i < 8; i++)
        #pragma unroll
        for (int u = 0; u < 5; u++) acc[i][u] = 0ULL;

    #pragma unroll 5
    for (int kp = 0; kp < HDIM / 2; kp++) {
        u64 b2[5];
        #pragma unroll
        for (int u = 0; u < 5; u++)
            b2[u] = *(const u64*)(sB + (tx * 5 + u) * 102 + 2 * kp);
        #pragma unroll
        for (int i = 0; i < 8; i++) {
            u64 a2 = *(const u64*)(sA + (ty * 8 + i) * HDIM + 2 * kp);
            #pragma unroll
            for (int u = 0; u < 5; u++)
                acc[i][u] = ffma2(a2, b2[u], acc[i][u]);
        }
    }

    float bias[5];
    #pragma unroll
    for (int u = 0; u < 5; u++) {
        int col = cbase + tx * 5 + u;
        bias[u] = bih[col] + bhh[col];
    }
    #pragma unroll
    for (int i = 0; i < 8; i++) {
        size_t row = rbase + ty * 8 + i;
        #pragma unroll
        for (int u = 0; u < 5; u++)
            g_pre1[row * GDIM + cbase + tx * 5 + u] = hsum2(acc[i][u]) + bias[u];
    }
}

// ============================================================================
// Layer-1 recurrence (pre1 precomputed) + fused 10x100 FC.
// Same 4-batch-per-thread structure.
// ============================================================================
__global__ void __launch_bounds__(NT1, 1) lstm_layer1_kernel(
    const float* __restrict__ Whh,    // [400][100]
    const float* __restrict__ fcw,    // [10][100]
    const float* __restrict__ fcb,    // [10]
    float* __restrict__ out)          // [1024][10]
{
    extern __shared__ float sm[];
    float* sW  = sm;                  // 400*100
    float* sH0 = sW + GDIM * HDIM;    // 800
    float* sH1 = sH0 + BPB * HDIM;    // 800

    const int tid = threadIdx.x;
    const int j0  = tid >> 1;
    const int bh  = tid & 1;
    const int bB  = 4 * bh;
    const int bg0 = blockIdx.x * BPB;

    for (int lin = tid; lin < GDIM * HDIM; lin += NT1) sW[lin] = Whh[lin];
    for (int lin = tid; lin < BPB * HDIM; lin += NT1) sH0[lin] = 0.0f;
    __syncthreads();

    const ulonglong2* wp0 = (const ulonglong2*)(sW + (0 * HDIM + j0) * HDIM);
    const ulonglong2* wp1 = (const ulonglong2*)(sW + (1 * HDIM + j0) * HDIM);
    const ulonglong2* wp2 = (const ulonglong2*)(sW + (2 * HDIM + j0) * HDIM);
    const ulonglong2* wp3 = (const ulonglong2*)(sW + (3 * HDIM + j0) * HDIM);
    const float* pbase = g_pre1 + (size_t)(bg0 + bB) * GDIM + j0;

    float c[4] = {0.0f, 0.0f, 0.0f, 0.0f};
    float* sHr = sH0;
    float* sHw = sH1;

    for (int t = 0; t < TT; t++) {
        // prefetch this step's pre-activations (L2/DRAM latency hidden by matvec)
        float p[4][4];
        const float* pr = pbase + (size_t)t * BATCH * GDIM;
        #pragma unroll
        for (int u = 0; u < 4; u++) {
            p[u][0] = pr[u * GDIM + 0 * HDIM];
            p[u][1] = pr[u * GDIM + 1 * HDIM];
            p[u][2] = pr[u * GDIM + 2 * HDIM];
            p[u][3] = pr[u * GDIM + 3 * HDIM];
        }

        u64 acc[4][4];
        #pragma unroll
        for (int g = 0; g < 4; g++)
            #pragma unroll
            for (int u = 0; u < 4; u++) acc[g][u] = 0ULL;

        const ulonglong2* hp0 = (const ulonglong2*)(sHr + (bB + 0) * HDIM);
        const ulonglong2* hp1 = (const ulonglong2*)(sHr + (bB + 1) * HDIM);
        const ulonglong2* hp2 = (const ulonglong2*)(sHr + (bB + 2) * HDIM);
        const ulonglong2* hp3 = (const ulonglong2*)(sHr + (bB + 3) * HDIM);

        #pragma unroll
        for (int k4 = 0; k4 < HDIM / 4; k4++) {
            ulonglong2 h0 = hp0[k4];
            ulonglong2 h1 = hp1[k4];
            ulonglong2 h2 = hp2[k4];
            ulonglong2 h3 = hp3[k4];
            ulonglong2 w;
            w = wp0[k4];
            acc[0][0] = ffma2(w.x, h0.x, acc[0][0]); acc[0][0] = ffma2(w.y, h0.y, acc[0][0]);
            acc[0][1] = ffma2(w.x, h1.x, acc[0][1]); acc[0][1] = ffma2(w.y, h1.y, acc[0][1]);
            acc[0][2] = ffma2(w.x, h2.x, acc[0][2]); acc[0][2] = ffma2(w.y, h2.y, acc[0][2]);
            acc[0][3] = ffma2(w.x, h3.x, acc[0][3]); acc[0][3] = ffma2(w.y, h3.y, acc[0][3]);
            w = wp1[k4];
            acc[1][0] = ffma2(w.x, h0.x, acc[1][0]); acc[1][0] = ffma2(w.y, h0.y, acc[1][0]);
            acc[1][1] = ffma2(w.x, h1.x, acc[1][1]); acc[1][1] = ffma2(w.y, h1.y, acc[1][1]);
            acc[1][2] = ffma2(w.x, h2.x, acc[1][2]); acc[1][2] = ffma2(w.y, h2.y, acc[1][2]);
            acc[1][3] = ffma2(w.x, h3.x, acc[1][3]); acc[1][3] = ffma2(w.y, h3.y, acc[1][3]);
            w = wp2[k4];
            acc[2][0] = ffma2(w.x, h0.x, acc[2][0]); acc[2][0] = ffma2(w.y, h0.y, acc[2][0]);
            acc[2][1] = ffma2(w.x, h1.x, acc[2][1]); acc[2][1] = ffma2(w.y, h1.y, acc[2][1]);
            acc[2][2] = ffma2(w.x, h2.x, acc[2][2]); acc[2][2] = ffma2(w.y, h2.y, acc[2][2]);
            acc[2][3] = ffma2(w.x, h3.x, acc[2][3]); acc[2][3] = ffma2(w.y, h3.y, acc[2][3]);
            w = wp3[k4];
            acc[3][0] = ffma2(w.x, h0.x, acc[3][0]); acc[3][0] = ffma2(w.y, h0.y, acc[3][0]);
            acc[3][1] = ffma2(w.x, h1.x, acc[3][1]); acc[3][1] = ffma2(w.y, h1.y, acc[3][1]);
            acc[3][2] = ffma2(w.x, h2.x, acc[3][2]); acc[3][2] = ffma2(w.y, h2.y, acc[3][2]);
            acc[3][3] = ffma2(w.x, h3.x, acc[3][3]); acc[3][3] = ffma2(w.y, h3.y, acc[3][3]);
        }

        #pragma unroll
        for (int u = 0; u < 4; u++) {
            float gi = hsum2(acc[0][u]) + p[u][0];
            float gf = hsum2(acc[1][u]) + p[u][1];
            float gg = hsum2(acc[2][u]) + p[u][2];
            float go = hsum2(acc[3][u]) + p[u][3];
            c[u] = sigmf(gf) * c[u] + sigmf(gi) * tanh_fast(gg);
            sHw[(bB + u) * HDIM + j0] = sigmf(go) * tanh_fast(c[u]);
        }

        float* tmp = sHr; sHr = sHw; sHw = tmp;
        __syncthreads();
    }

    if (tid < BPB * 10) {
        int bb = tid / 10, o = tid % 10;
        float acc = fcb[o];
        const float* wrow = fcw + o * HDIM;
        const float* hrow = sHr + bb * HDIM;
        #pragma unroll 4
        for (int k = 0; k < HDIM; k++) acc = fmaf(wrow[k], hrow[k], acc);
        out[(bg0 + bb) * 10 + o] = acc;
    }
}

// ============================================================================
// launch: plain serial launches on the default stream. No streams, no events,
// no allocations of any kind (R11's guard violation came from stream/event
// creation; overlap bought nothing anyway).
// ============================================================================
extern "C" void kernel_launch(void* const* d_in, const int* in_sizes, int n_in,
                              void* d_out, int out_size)
{
    (void)in_sizes; (void)n_in; (void)out_size;
    const float* x    = (const float*)d_in[0];
    const float* Wih0 = (const float*)d_in[1];
    const float* Whh0 = (const float*)d_in[2];
    const float* bih0 = (const float*)d_in[3];
    const float* bhh0 = (const float*)d_in[4];
    const float* Wih1 = (const float*)d_in[5];
    const float* Whh1 = (const float*)d_in[6];
    const float* bih1 = (const float*)d_in[7];
    const float* bhh1 = (const float*)d_in[8];
    const float* fcw  = (const float*)d_in[9];
    const float* fcb  = (const float*)d_in[10];
    float* out = (float*)d_out;

    const size_t smem0 = (size_t)(GDIM * HDIM + GDIM * 4 + GDIM + 2 * BPB * HDIM) * 4;
    const size_t smemA = (size_t)(GA_MT * HDIM + GA_NT * 102) * 4;
    const size_t smem1 = (size_t)(GDIM * HDIM + 2 * BPB * HDIM) * 4;

    cudaFuncSetAttribute(lstm_layer0_kernel, cudaFuncAttributeMaxDynamicSharedMemorySize, (int)smem0);
    cudaFuncSetAttribute(gemm_ih1_kernel,    cudaFuncAttributeMaxDynamicSharedMemorySize, (int)smemA);
    cudaFuncSetAttribute(lstm_layer1_kernel, cudaFuncAttributeMaxDynamicSharedMemorySize, (int)smem1);

    lstm_layer0_kernel<<<NB1, NT1, smem0>>>(x, Wih0, Whh0, bih0, bhh0);

    dim3 g2a(GDIM / GA_NT, (TT * BATCH) / GA_MT);  // (5, 8192)
    gemm_ih1_kernel<<<g2a, 256, smemA>>>(Wih1, bih1, bhh1);

    lstm_layer1_kernel<<<NB1, NT1, smem1>>>(Whh1, fcw, fcb, out);
}

// round 13
// speedup vs baseline: 1.4042x; 1.4042x over previous
#include <cuda_runtime.h>
#include <math.h>

#define TT    1024
#define BATCH 1024
#define HDIM  100
#define GDIM  400
#define BPB   8              // batch elems per block
#define NB1   (BATCH / BPB)  // 128 persistent blocks
#define NT1   400            // thread <-> (batch-pair bp in 0..3, j0 in 0..99)

typedef unsigned long long u64;

__device__ float g_h1[(size_t)TT * BATCH * HDIM];    // layer-0 hidden states
__device__ float g_pre1[(size_t)TT * BATCH * GDIM];  // layer-1 gate pre-activations

__device__ __forceinline__ float sigmf(float x) { return 1.0f / (1.0f + __expf(-x)); }
__device__ __forceinline__ float tanh_fast(float x) {
    float t = __expf(2.0f * x);
    return 1.0f - __fdividef(2.0f, t + 1.0f);
}
__device__ __forceinline__ u64 ffma2(u64 a, u64 b, u64 c) {
    u64 d;
    asm("fma.rn.f32x2 %0, %1, %2, %3;" : "=l"(d) : "l"(a), "l"(b), "l"(c));
    return d;
}
__device__ __forceinline__ float hsum2(u64 v) {
    float lo, hi;
    asm("mov.b64 {%0, %1}, %2;" : "=f"(lo), "=f"(hi) : "l"(v));
    return lo + hi;
}

// ============================================================================
// Layer-0 recurrence (exact R5 structure — best measured). Thread owns
// (batch-pair, j0): 8 gates, 2 in-register cells; one barrier/step.
// ============================================================================
__global__ void __launch_bounds__(NT1, 1) lstm_layer0_kernel(
    const float* __restrict__ x,      // [1024][3][1024]
    const float* __restrict__ Wih,    // [400][3]
    const float* __restrict__ Whh,    // [400][100]
    const float* __restrict__ bih,
    const float* __restrict__ bhh)
{
    extern __shared__ float sm[];
    float* sW    = sm;                   // 400*100
    float* sWin  = sW + GDIM * HDIM;     // 400*4
    float* sBias = sWin + GDIM * 4;      // 400
    float* sH0   = sBias + GDIM;         // 800
    float* sH1   = sH0 + BPB * HDIM;     // 800

    const int tid = threadIdx.x;
    const int bp  = tid & 3;
    const int j0  = tid >> 2;            // 0..99
    const int b0  = 2 * bp, b1 = b0 + 1;
    const int bg0 = blockIdx.x * BPB;

    for (int lin = tid; lin < GDIM * HDIM; lin += NT1) sW[lin] = Whh[lin];
    for (int lin = tid; lin < GDIM * 3; lin += NT1)
        sWin[(lin / 3) * 4 + (lin % 3)] = Wih[lin];
    for (int lin = tid; lin < GDIM; lin += NT1) sBias[lin] = bih[lin] + bhh[lin];
    for (int lin = tid; lin < BPB * HDIM; lin += NT1) sH0[lin] = 0.0f;
    __syncthreads();

    float bi[4], wi[4][3];
    #pragma unroll
    for (int g = 0; g < 4; g++) {
        bi[g] = sBias[g * HDIM + j0];
        wi[g][0] = sWin[(g * HDIM + j0) * 4 + 0];
        wi[g][1] = sWin[(g * HDIM + j0) * 4 + 1];
        wi[g][2] = sWin[(g * HDIM + j0) * 4 + 2];
    }
    const ulonglong2* wp0 = (const ulonglong2*)(sW + (0 * HDIM + j0) * HDIM);
    const ulonglong2* wp1 = (const ulonglong2*)(sW + (1 * HDIM + j0) * HDIM);
    const ulonglong2* wp2 = (const ulonglong2*)(sW + (2 * HDIM + j0) * HDIM);
    const ulonglong2* wp3 = (const ulonglong2*)(sW + (3 * HDIM + j0) * HDIM);
    const float* xa = x + (size_t)(bg0 + b0) * 3072;
    const float* xb = x + (size_t)(bg0 + b1) * 3072;

    float c0 = 0.0f, c1 = 0.0f;
    float* sHr = sH0;
    float* sHw = sH1;

    for (int t = 0; t < TT; t++) {
        float xa0 = xa[t], xa1 = xa[1024 + t], xa2 = xa[2048 + t];
        float xb0 = xb[t], xb1 = xb[1024 + t], xb2 = xb[2048 + t];

        u64 a00 = 0, a01 = 0, a02 = 0, a03 = 0;   // batch b0, gates i f g o
        u64 a10 = 0, a11 = 0, a12 = 0, a13 = 0;   // batch b1
        const ulonglong2* hpa = (const ulonglong2*)(sHr + b0 * HDIM);
        const ulonglong2* hpb = (const ulonglong2*)(sHr + b1 * HDIM);
        #pragma unroll
        for (int k4 = 0; k4 < HDIM / 4; k4++) {
            ulonglong2 ha = hpa[k4];
            ulonglong2 hb = hpb[k4];
            ulonglong2 w;
            w = wp0[k4];
            a00 = ffma2(w.x, ha.x, a00); a00 = ffma2(w.y, ha.y, a00);
            a10 = ffma2(w.x, hb.x, a10); a10 = ffma2(w.y, hb.y, a10);
            w = wp1[k4];
            a01 = ffma2(w.x, ha.x, a01); a01 = ffma2(w.y, ha.y, a01);
            a11 = ffma2(w.x, hb.x, a11); a11 = ffma2(w.y, hb.y, a11);
            w = wp2[k4];
            a02 = ffma2(w.x, ha.x, a02); a02 = ffma2(w.y, ha.y, a02);
            a12 = ffma2(w.x, hb.x, a12); a12 = ffma2(w.y, hb.y, a12);
            w = wp3[k4];
            a03 = ffma2(w.x, ha.x, a03); a03 = ffma2(w.y, ha.y, a03);
            a13 = ffma2(w.x, hb.x, a13); a13 = ffma2(w.y, hb.y, a13);
        }

        float gi0 = hsum2(a00) + bi[0] + wi[0][0]*xa0 + wi[0][1]*xa1 + wi[0][2]*xa2;
        float gf0 = hsum2(a01) + bi[1] + wi[1][0]*xa0 + wi[1][1]*xa1 + wi[1][2]*xa2;
        float gg0 = hsum2(a02) + bi[2] + wi[2][0]*xa0 + wi[2][1]*xa1 + wi[2][2]*xa2;
        float go0 = hsum2(a03) + bi[3] + wi[3][0]*xa0 + wi[3][1]*xa1 + wi[3][2]*xa2;
        float gi1 = hsum2(a10) + bi[0] + wi[0][0]*xb0 + wi[0][1]*xb1 + wi[0][2]*xb2;
        float gf1 = hsum2(a11) + bi[1] + wi[1][0]*xb0 + wi[1][1]*xb1 + wi[1][2]*xb2;
        float gg1 = hsum2(a12) + bi[2] + wi[2][0]*xb0 + wi[2][1]*xb1 + wi[2][2]*xb2;
        float go1 = hsum2(a13) + bi[3] + wi[3][0]*xb0 + wi[3][1]*xb1 + wi[3][2]*xb2;

        c0 = sigmf(gf0) * c0 + sigmf(gi0) * tanh_fast(gg0);
        c1 = sigmf(gf1) * c1 + sigmf(gi1) * tanh_fast(gg1);
        float h0 = sigmf(go0) * tanh_fast(c0);
        float h1v = sigmf(go1) * tanh_fast(c1);

        sHw[b0 * HDIM + j0] = h0;
        sHw[b1 * HDIM + j0] = h1v;
        size_t rowbase = ((size_t)t * BATCH + bg0);
        g_h1[(rowbase + b0) * HDIM + j0] = h0;
        g_h1[(rowbase + b1) * HDIM + j0] = h1v;

        float* tmp = sHr; sHr = sHw; sHw = tmp;
        __syncthreads();
    }
}

// ============================================================================
// Layer-1 input GEMM: pre1[r][j] = bias[j] + sum_k h1[r][k]*W_ih1[j][k]
// 128x80 tile, 256 threads, thread tile 8x5. NEW: k-quad LDS.128 loads for
// both A (stride 100, 16B-aligned) and B (stride padded to 104).
// Per 4-k iter: 13 LDS.128 -> 80 FFMA2 (was 26 LDS.64 -> 80).
// ============================================================================
#define GA_MT 128
#define GA_NT 80
#define SB_STR 104
__global__ void __launch_bounds__(256, 2) gemm_ih1_kernel(
    const float* __restrict__ W,      // [400][100]
    const float* __restrict__ bih,
    const float* __restrict__ bhh)
{
    extern __shared__ float sm[];
    float* sA = sm;                    // 128*100 (row stride 100: 400B, 16B-aligned)
    float* sB = sA + GA_MT * HDIM;     // 80*104  (col stride 104: 416B, 16B-aligned)

    const int tid = threadIdx.x;
    const size_t rbase = (size_t)blockIdx.y * GA_MT;
    const int cbase = blockIdx.x * GA_NT;

    for (int lin = tid; lin < GA_MT * HDIM; lin += 256)
        sA[lin] = g_h1[rbase * HDIM + lin];
    for (int lin = tid; lin < GA_NT * SB_STR; lin += 256) {
        int row = lin / SB_STR, k = lin % SB_STR;
        sB[lin] = (k < HDIM) ? W[(size_t)(cbase + row) * HDIM + k] : 0.0f;
    }
    __syncthreads();

    const int tx = tid & 15;   // 5 cols each
    const int ty = tid >> 4;   // 8 rows each

    const float* pB = sB + (tx * 5) * SB_STR;
    const float* pA = sA + (ty * 8) * HDIM;

    u64 acc[8][5];
    #pragma unroll
    for (int i = 0; i < 8; i++)
        #pragma unroll
        for (int u = 0; u < 5; u++) acc[i][u] = 0ULL;

    #pragma unroll
    for (int k4 = 0; k4 < HDIM / 4; k4++) {
        ulonglong2 b2[5];
        #pragma unroll
        for (int u = 0; u < 5; u++)
            b2[u] = *(const ulonglong2*)(pB + u * SB_STR + k4 * 4);
        // A staged in two 4-row halves to bound live registers
        #pragma unroll
        for (int half = 0; half < 2; half++) {
            ulonglong2 a2[4];
            #pragma unroll
            for (int i = 0; i < 4; i++)
                a2[i] = *(const ulonglong2*)(pA + (half * 4 + i) * HDIM + k4 * 4);
            #pragma unroll
            for (int i = 0; i < 4; i++) {
                #pragma unroll
                for (int u = 0; u < 5; u++) {
                    acc[half * 4 + i][u] = ffma2(a2[i].x, b2[u].x, acc[half * 4 + i][u]);
                    acc[half * 4 + i][u] = ffma2(a2[i].y, b2[u].y, acc[half * 4 + i][u]);
                }
            }
        }
    }

    float bias[5];
    #pragma unroll
    for (int u = 0; u < 5; u++) {
        int col = cbase + tx * 5 + u;
        bias[u] = bih[col] + bhh[col];
    }
    #pragma unroll
    for (int i = 0; i < 8; i++) {
        size_t row = rbase + ty * 8 + i;
        #pragma unroll
        for (int u = 0; u < 5; u++)
            g_pre1[row * GDIM + cbase + tx * 5 + u] = hsum2(acc[i][u]) + bias[u];
    }
}

// ============================================================================
// Layer-1 recurrence (exact R5 structure) + fused 10x100 FC.
// ============================================================================
__global__ void __launch_bounds__(NT1, 1) lstm_layer1_kernel(
    const float* __restrict__ Whh,    // [400][100]
    const float* __restrict__ fcw,    // [10][100]
    const float* __restrict__ fcb,    // [10]
    float* __restrict__ out)          // [1024][10]
{
    extern __shared__ float sm[];
    float* sW  = sm;                  // 400*100
    float* sH0 = sW + GDIM * HDIM;    // 800
    float* sH1 = sH0 + BPB * HDIM;    // 800

    const int tid = threadIdx.x;
    const int bp  = tid & 3;
    const int j0  = tid >> 2;
    const int b0  = 2 * bp, b1 = b0 + 1;
    const int bg0 = blockIdx.x * BPB;

    for (int lin = tid; lin < GDIM * HDIM; lin += NT1) sW[lin] = Whh[lin];
    for (int lin = tid; lin < BPB * HDIM; lin += NT1) sH0[lin] = 0.0f;
    __syncthreads();

    const ulonglong2* wp0 = (const ulonglong2*)(sW + (0 * HDIM + j0) * HDIM);
    const ulonglong2* wp1 = (const ulonglong2*)(sW + (1 * HDIM + j0) * HDIM);
    const ulonglong2* wp2 = (const ulonglong2*)(sW + (2 * HDIM + j0) * HDIM);
    const ulonglong2* wp3 = (const ulonglong2*)(sW + (3 * HDIM + j0) * HDIM);

    float c0 = 0.0f, c1 = 0.0f;
    float* sHr = sH0;
    float* sHw = sH1;

    for (int t = 0; t < TT; t++) {
        const float* pra = g_pre1 + ((size_t)t * BATCH + bg0 + b0) * GDIM + j0;
        const float* prb = g_pre1 + ((size_t)t * BATCH + bg0 + b1) * GDIM + j0;
        float p00 = pra[0], p01 = pra[HDIM], p02 = pra[2 * HDIM], p03 = pra[3 * HDIM];
        float p10 = prb[0], p11 = prb[HDIM], p12 = prb[2 * HDIM], p13 = prb[3 * HDIM];

        u64 a00 = 0, a01 = 0, a02 = 0, a03 = 0;
        u64 a10 = 0, a11 = 0, a12 = 0, a13 = 0;
        const ulonglong2* hpa = (const ulonglong2*)(sHr + b0 * HDIM);
        const ulonglong2* hpb = (const ulonglong2*)(sHr + b1 * HDIM);
        #pragma unroll
        for (int k4 = 0; k4 < HDIM / 4; k4++) {
            ulonglong2 ha = hpa[k4];
            ulonglong2 hb = hpb[k4];
            ulonglong2 w;
            w = wp0[k4];
            a00 = ffma2(w.x, ha.x, a00); a00 = ffma2(w.y, ha.y, a00);
            a10 = ffma2(w.x, hb.x, a10); a10 = ffma2(w.y, hb.y, a10);
            w = wp1[k4];
            a01 = ffma2(w.x, ha.x, a01); a01 = ffma2(w.y, ha.y, a01);
            a11 = ffma2(w.x, hb.x, a11); a11 = ffma2(w.y, hb.y, a11);
            w = wp2[k4];
            a02 = ffma2(w.x, ha.x, a02); a02 = ffma2(w.y, ha.y, a02);
            a12 = ffma2(w.x, hb.x, a12); a12 = ffma2(w.y, hb.y, a12);
            w = wp3[k4];
            a03 = ffma2(w.x, ha.x, a03); a03 = ffma2(w.y, ha.y, a03);
            a13 = ffma2(w.x, hb.x, a13); a13 = ffma2(w.y, hb.y, a13);
        }

        float gi0 = hsum2(a00) + p00, gf0 = hsum2(a01) + p01;
        float gg0 = hsum2(a02) + p02, go0 = hsum2(a03) + p03;
        float gi1 = hsum2(a10) + p10, gf1 = hsum2(a11) + p11;
        float gg1 = hsum2(a12) + p12, go1 = hsum2(a13) + p13;

        c0 = sigmf(gf0) * c0 + sigmf(gi0) * tanh_fast(gg0);
        c1 = sigmf(gf1) * c1 + sigmf(gi1) * tanh_fast(gg1);
        sHw[b0 * HDIM + j0] = sigmf(go0) * tanh_fast(c0);
        sHw[b1 * HDIM + j0] = sigmf(go1) * tanh_fast(c1);

        float* tmp = sHr; sHr = sHw; sHw = tmp;
        __syncthreads();
    }

    if (tid < BPB * 10) {
        int bb = tid / 10, o = tid % 10;
        float acc = fcb[o];
        const float* wrow = fcw + o * HDIM;
        const float* hrow = sHr + bb * HDIM;
        #pragma unroll 4
        for (int k = 0; k < HDIM; k++) acc = fmaf(wrow[k], hrow[k], acc);
        out[(bg0 + bb) * 10 + o] = acc;
    }
}

// ============================================================================
// launch: plain serial launches on the default stream (no allocations).
// ============================================================================
extern "C" void kernel_launch(void* const* d_in, const int* in_sizes, int n_in,
                              void* d_out, int out_size)
{
    (void)in_sizes; (void)n_in; (void)out_size;
    const float* x    = (const float*)d_in[0];
    const float* Wih0 = (const float*)d_in[1];
    const float* Whh0 = (const float*)d_in[2];
    const float* bih0 = (const float*)d_in[3];
    const float* bhh0 = (const float*)d_in[4];
    const float* Wih1 = (const float*)d_in[5];
    const float* Whh1 = (const float*)d_in[6];
    const float* bih1 = (const float*)d_in[7];
    const float* bhh1 = (const float*)d_in[8];
    const float* fcw  = (const float*)d_in[9];
    const float* fcb  = (const float*)d_in[10];
    float* out = (float*)d_out;

    const size_t smem0 = (size_t)(GDIM * HDIM + GDIM * 4 + GDIM + 2 * BPB * HDIM) * 4;
    const size_t smemA = (size_t)(GA_MT * HDIM + GA_NT * SB_STR) * 4;
    const size_t smem1 = (size_t)(GDIM * HDIM + 2 * BPB * HDIM) * 4;

    cudaFuncSetAttribute(lstm_layer0_kernel, cudaFuncAttributeMaxDynamicSharedMemorySize, (int)smem0);
    cudaFuncSetAttribute(gemm_ih1_kernel,    cudaFuncAttributeMaxDynamicSharedMemorySize, (int)smemA);
    cudaFuncSetAttribute(lstm_layer1_kernel, cudaFuncAttributeMaxDynamicSharedMemorySize, (int)smem1);

    lstm_layer0_kernel<<<NB1, NT1, smem0>>>(x, Wih0, Whh0, bih0, bhh0);

    dim3 g2a(GDIM / GA_NT, (TT * BATCH) / GA_MT);  // (5, 8192)
    gemm_ih1_kernel<<<g2a, 256, smemA>>>(Wih1, bih1, bhh1);

    lstm_layer1_kernel<<<NB1, NT1, smem1>>>(Whh1, fcw, fcb, out);
}